// round 14
// baseline (speedup 1.0000x reference)
#include <cuda_runtime.h>
#include <cuda_bf16.h>
#include <cstdint>

#define NN  50000
#define EIN 800000
#define FIN 256
#define C1  64       // H1*D1
#define C2  128      // H2*C
#define NH  8
#define MAXD 64      // padded CSR slots per node (Poisson(16): P(deg>64) ~ 1e-21)
#define SPAD 68      // s_al row stride (floats): 272B, 16B-aligned rows
#define NEG_SLOPE 0.2f

// ---------------- scratch (device globals; no allocation allowed) ----------
__device__ __align__(16) float g_xw1[NN * C1];
__device__ __align__(16) float g_al1s[NN * NH];
__device__ __align__(16) float g_al1d[NN * NH];
__device__ __align__(16) float g_h1[NN * C1];
__device__ __align__(16) float g_xw2[NN * C2];
__device__ __align__(16) float g_al2s[NN * NH];
__device__ __align__(16) float g_al2d[NN * NH];
__device__ __align__(16) int   g_cur[NN];
__device__ int   g_srcs[NN * MAXD];
__device__ int   g_eid[NN * MAXD];

// ---------------- helpers --------------------------------------------------
__device__ __forceinline__ uint32_t pkbf(float a, float b) {
    __nv_bfloat162 t = __floats2bfloat162_rn(a, b);
    return *(uint32_t*)&t;
}
__device__ __forceinline__ void mma_bf16(float* d, uint32_t a0, uint32_t a1,
                                         uint32_t a2, uint32_t a3,
                                         uint32_t b0, uint32_t b1) {
    asm volatile(
        "mma.sync.aligned.m16n8k16.row.col.f32.bf16.bf16.f32 "
        "{%0,%1,%2,%3}, {%4,%5,%6,%7}, {%8,%9}, {%0,%1,%2,%3};"
        : "+f"(d[0]), "+f"(d[1]), "+f"(d[2]), "+f"(d[3])
        : "r"(a0), "r"(a1), "r"(a2), "r"(a3), "r"(b0), "r"(b1));
}

// ---------------- CSR build (padded, no scan) ------------------------------
__global__ void zero_cur_k() {
    int i = blockIdx.x * blockDim.x + threadIdx.x;
    if (i * 4 + 3 < NN) *(int4*)&g_cur[i * 4] = make_int4(0, 0, 0, 0);
    else for (int n = i * 4; n < NN; n++) g_cur[n] = 0;
}

__global__ void scatter_k(const int* __restrict__ ei) {
    const int NE8 = EIN / 8;
    int t = blockIdx.x * blockDim.x + threadIdx.x;
    if (t < NE8) {
        int e = t * 8;
        int4 s0 = *(const int4*)&ei[e];
        int4 s1 = *(const int4*)&ei[e + 4];
        int4 d0 = *(const int4*)&ei[EIN + e];
        int4 d1 = *(const int4*)&ei[EIN + e + 4];
        int p;
        p = atomicAdd(&g_cur[d0.x], 1); if (p < MAXD) { g_srcs[d0.x * MAXD + p] = s0.x; g_eid[d0.x * MAXD + p] = e; }
        p = atomicAdd(&g_cur[d0.y], 1); if (p < MAXD) { g_srcs[d0.y * MAXD + p] = s0.y; g_eid[d0.y * MAXD + p] = e + 1; }
        p = atomicAdd(&g_cur[d0.z], 1); if (p < MAXD) { g_srcs[d0.z * MAXD + p] = s0.z; g_eid[d0.z * MAXD + p] = e + 2; }
        p = atomicAdd(&g_cur[d0.w], 1); if (p < MAXD) { g_srcs[d0.w * MAXD + p] = s0.w; g_eid[d0.w * MAXD + p] = e + 3; }
        p = atomicAdd(&g_cur[d1.x], 1); if (p < MAXD) { g_srcs[d1.x * MAXD + p] = s1.x; g_eid[d1.x * MAXD + p] = e + 4; }
        p = atomicAdd(&g_cur[d1.y], 1); if (p < MAXD) { g_srcs[d1.y * MAXD + p] = s1.y; g_eid[d1.y * MAXD + p] = e + 5; }
        p = atomicAdd(&g_cur[d1.z], 1); if (p < MAXD) { g_srcs[d1.z * MAXD + p] = s1.z; g_eid[d1.z * MAXD + p] = e + 6; }
        p = atomicAdd(&g_cur[d1.w], 1); if (p < MAXD) { g_srcs[d1.w * MAXD + p] = s1.w; g_eid[d1.w * MAXD + p] = e + 7; }
    } else {
        int n0 = (t - NE8) * 8;
#pragma unroll
        for (int k = 0; k < 8; k++) {
            int n = n0 + k;
            if (n < NN) {
                int p = atomicAdd(&g_cur[n], 1);
                if (p < MAXD) { g_srcs[n * MAXD + p] = n; g_eid[n * MAXD + p] = EIN + n; }
            }
        }
    }
}

// ============ GEMM1 (mma.sync bf16x3): xw1 = x @ W1, fused al1 =============
#define S1ROW 144
#define G1_WS  0
#define G1_AHI 512
#define G1_ALO (G1_AHI + 128 * S1ROW)
#define G1_BHI (G1_ALO + 128 * S1ROW)
#define G1_BLO (G1_BHI + 64 * S1ROW)
#define G1_SMEM (G1_BLO + 64 * S1ROW)

__global__ __launch_bounds__(256) void gemm1_m(
    const float* __restrict__ A, const float* __restrict__ W,
    const float* __restrict__ a1s, const float* __restrict__ a1d) {
    extern __shared__ char sm[];
    float* ws = (float*)(sm + G1_WS);
    int tid = threadIdx.x, wid = tid >> 5, lid = tid & 31;
    int g = lid >> 2, c = lid & 3;
    int row0 = blockIdx.x * 128;

    if (tid < 64) ws[tid] = a1s[tid];
    else if (tid < 128) ws[tid] = a1d[tid - 64];

    float d[8][4];
#pragma unroll
    for (int nt = 0; nt < 8; nt++)
#pragma unroll
        for (int q = 0; q < 4; q++) d[nt][q] = 0.f;

    for (int kc = 0; kc < 4; kc++) {
        if (kc) __syncthreads();
#pragma unroll
        for (int it = 0; it < 8; it++) {
            int idx = tid + it * 256;
            int r = idx >> 4, k = (idx & 15) << 2;
            int gr = row0 + r;
            float4 v = (gr < NN) ? *(const float4*)&A[(size_t)gr * FIN + kc * 64 + k]
                                 : make_float4(0.f, 0.f, 0.f, 0.f);
            uint32_t h0 = pkbf(v.x, v.y), h1 = pkbf(v.z, v.w);
            uint32_t l0 = pkbf(v.x - __bfloat162float(__float2bfloat16(v.x)),
                               v.y - __bfloat162float(__float2bfloat16(v.y)));
            uint32_t l1 = pkbf(v.z - __bfloat162float(__float2bfloat16(v.z)),
                               v.w - __bfloat162float(__float2bfloat16(v.w)));
            *(uint2*)(sm + G1_AHI + r * S1ROW + k * 2) = make_uint2(h0, h1);
            *(uint2*)(sm + G1_ALO + r * S1ROW + k * 2) = make_uint2(l0, l1);
        }
#pragma unroll
        for (int it = 0; it < 4; it++) {
            int idx = tid + it * 256;
            int n = idx & 63, k = (idx >> 6) << 2;
            float v0 = W[(kc * 64 + k) * 64 + n];
            float v1 = W[(kc * 64 + k + 1) * 64 + n];
            float v2 = W[(kc * 64 + k + 2) * 64 + n];
            float v3 = W[(kc * 64 + k + 3) * 64 + n];
            uint32_t h0 = pkbf(v0, v1), h1 = pkbf(v2, v3);
            uint32_t l0 = pkbf(v0 - __bfloat162float(__float2bfloat16(v0)),
                               v1 - __bfloat162float(__float2bfloat16(v1)));
            uint32_t l1 = pkbf(v2 - __bfloat162float(__float2bfloat16(v2)),
                               v3 - __bfloat162float(__float2bfloat16(v3)));
            *(uint2*)(sm + G1_BHI + n * S1ROW + k * 2) = make_uint2(h0, h1);
            *(uint2*)(sm + G1_BLO + n * S1ROW + k * 2) = make_uint2(l0, l1);
        }
        __syncthreads();

#pragma unroll
        for (int ks = 0; ks < 4; ks++) {
            int k0 = ks * 16;
            const char* pah = sm + G1_AHI + (wid * 16 + g) * S1ROW + (k0 + c * 2) * 2;
            const char* pal = sm + G1_ALO + (wid * 16 + g) * S1ROW + (k0 + c * 2) * 2;
            uint32_t ah0 = *(const uint32_t*)(pah);
            uint32_t ah1 = *(const uint32_t*)(pah + 8 * S1ROW);
            uint32_t ah2 = *(const uint32_t*)(pah + 16);
            uint32_t ah3 = *(const uint32_t*)(pah + 8 * S1ROW + 16);
            uint32_t al0 = *(const uint32_t*)(pal);
            uint32_t al1 = *(const uint32_t*)(pal + 8 * S1ROW);
            uint32_t al2 = *(const uint32_t*)(pal + 16);
            uint32_t al3 = *(const uint32_t*)(pal + 8 * S1ROW + 16);
#pragma unroll
            for (int nt = 0; nt < 8; nt++) {
                const char* pbh = sm + G1_BHI + (nt * 8 + g) * S1ROW + (k0 + c * 2) * 2;
                const char* pbl = sm + G1_BLO + (nt * 8 + g) * S1ROW + (k0 + c * 2) * 2;
                uint32_t bh0 = *(const uint32_t*)(pbh);
                uint32_t bh1 = *(const uint32_t*)(pbh + 16);
                uint32_t bl0 = *(const uint32_t*)(pbl);
                uint32_t bl1 = *(const uint32_t*)(pbl + 16);
                mma_bf16(d[nt], ah0, ah1, ah2, ah3, bh0, bh1);
                mma_bf16(d[nt], ah0, ah1, ah2, ah3, bl0, bl1);
                mma_bf16(d[nt], al0, al1, al2, al3, bh0, bh1);
            }
        }
    }

    int r1 = row0 + wid * 16 + g, r2 = r1 + 8;
#pragma unroll
    for (int nt = 0; nt < 8; nt++) {
        if (r1 < NN) *(float2*)&g_xw1[(size_t)r1 * C1 + nt * 8 + c * 2] = make_float2(d[nt][0], d[nt][1]);
        if (r2 < NN) *(float2*)&g_xw1[(size_t)r2 * C1 + nt * 8 + c * 2] = make_float2(d[nt][2], d[nt][3]);
    }
#pragma unroll
    for (int h = 0; h < 8; h++) {
        int wcol = h * 8 + c * 2;
        float s1 = d[h][0] * ws[wcol] + d[h][1] * ws[wcol + 1];
        float t1 = d[h][0] * ws[64 + wcol] + d[h][1] * ws[64 + wcol + 1];
        float s2 = d[h][2] * ws[wcol] + d[h][3] * ws[wcol + 1];
        float t2 = d[h][2] * ws[64 + wcol] + d[h][3] * ws[64 + wcol + 1];
#pragma unroll
        for (int mk = 1; mk <= 2; mk <<= 1) {
            s1 += __shfl_xor_sync(0xffffffffu, s1, mk);
            t1 += __shfl_xor_sync(0xffffffffu, t1, mk);
            s2 += __shfl_xor_sync(0xffffffffu, s2, mk);
            t2 += __shfl_xor_sync(0xffffffffu, t2, mk);
        }
        if (c == 0) {
            if (r1 < NN) { g_al1s[r1 * NH + h] = s1; g_al1d[r1 * NH + h] = t1; }
            if (r2 < NN) { g_al1s[r2 * NH + h] = s2; g_al1d[r2 * NH + h] = t2; }
        }
    }
}

// ============ GEMM2 (mma.sync bf16x3): xw2 = h1 @ W2, fused al2 =============
#define G2_WS  0
#define G2_AHI 1024
#define G2_ALO (G2_AHI + 128 * S1ROW)
#define G2_BHI (G2_ALO + 128 * S1ROW)
#define G2_BLO (G2_BHI + 128 * S1ROW)
#define G2_SMEM (G2_BLO + 128 * S1ROW)

__global__ __launch_bounds__(256) void gemm2_m(
    const float* __restrict__ W,
    const float* __restrict__ a2s, const float* __restrict__ a2d) {
    extern __shared__ char sm[];
    float* ws = (float*)(sm + G2_WS);
    int tid = threadIdx.x, wid = tid >> 5, lid = tid & 31;
    int g = lid >> 2, c = lid & 3;
    int row0 = blockIdx.x * 128;

    if (tid < 128) ws[tid] = a2s[tid];
    else ws[tid] = a2d[tid - 128];

#pragma unroll
    for (int it = 0; it < 8; it++) {
        int idx = tid + it * 256;
        int r = idx >> 4, k = (idx & 15) << 2;
        int gr = row0 + r;
        float4 v = (gr < NN) ? *(const float4*)&g_h1[(size_t)gr * C1 + k]
                             : make_float4(0.f, 0.f, 0.f, 0.f);
        uint32_t h0 = pkbf(v.x, v.y), h1 = pkbf(v.z, v.w);
        uint32_t l0 = pkbf(v.x - __bfloat162float(__float2bfloat16(v.x)),
                           v.y - __bfloat162float(__float2bfloat16(v.y)));
        uint32_t l1 = pkbf(v.z - __bfloat162float(__float2bfloat16(v.z)),
                           v.w - __bfloat162float(__float2bfloat16(v.w)));
        *(uint2*)(sm + G2_AHI + r * S1ROW + k * 2) = make_uint2(h0, h1);
        *(uint2*)(sm + G2_ALO + r * S1ROW + k * 2) = make_uint2(l0, l1);
    }
#pragma unroll
    for (int it = 0; it < 8; it++) {
        int idx = tid + it * 256;
        int n = idx & 127, k = (idx >> 7) << 2;
        float v0 = W[(k) * 128 + n];
        float v1 = W[(k + 1) * 128 + n];
        float v2 = W[(k + 2) * 128 + n];
        float v3 = W[(k + 3) * 128 + n];
        uint32_t h0 = pkbf(v0, v1), h1 = pkbf(v2, v3);
        uint32_t l0 = pkbf(v0 - __bfloat162float(__float2bfloat16(v0)),
                           v1 - __bfloat162float(__float2bfloat16(v1)));
        uint32_t l1 = pkbf(v2 - __bfloat162float(__float2bfloat16(v2)),
                           v3 - __bfloat162float(__float2bfloat16(v3)));
        *(uint2*)(sm + G2_BHI + n * S1ROW + k * 2) = make_uint2(h0, h1);
        *(uint2*)(sm + G2_BLO + n * S1ROW + k * 2) = make_uint2(l0, l1);
    }
    __syncthreads();

    float d[16][4];
#pragma unroll
    for (int nt = 0; nt < 16; nt++)
#pragma unroll
        for (int q = 0; q < 4; q++) d[nt][q] = 0.f;

#pragma unroll
    for (int ks = 0; ks < 4; ks++) {
        int k0 = ks * 16;
        const char* pah = sm + G2_AHI + (wid * 16 + g) * S1ROW + (k0 + c * 2) * 2;
        const char* pal = sm + G2_ALO + (wid * 16 + g) * S1ROW + (k0 + c * 2) * 2;
        uint32_t ah0 = *(const uint32_t*)(pah);
        uint32_t ah1 = *(const uint32_t*)(pah + 8 * S1ROW);
        uint32_t ah2 = *(const uint32_t*)(pah + 16);
        uint32_t ah3 = *(const uint32_t*)(pah + 8 * S1ROW + 16);
        uint32_t al0 = *(const uint32_t*)(pal);
        uint32_t al1 = *(const uint32_t*)(pal + 8 * S1ROW);
        uint32_t al2 = *(const uint32_t*)(pal + 16);
        uint32_t al3 = *(const uint32_t*)(pal + 8 * S1ROW + 16);
#pragma unroll
        for (int nt = 0; nt < 16; nt++) {
            const char* pbh = sm + G2_BHI + (nt * 8 + g) * S1ROW + (k0 + c * 2) * 2;
            const char* pbl = sm + G2_BLO + (nt * 8 + g) * S1ROW + (k0 + c * 2) * 2;
            uint32_t bh0 = *(const uint32_t*)(pbh);
            uint32_t bh1 = *(const uint32_t*)(pbh + 16);
            uint32_t bl0 = *(const uint32_t*)(pbl);
            uint32_t bl1 = *(const uint32_t*)(pbl + 16);
            mma_bf16(d[nt], ah0, ah1, ah2, ah3, bh0, bh1);
            mma_bf16(d[nt], ah0, ah1, ah2, ah3, bl0, bl1);
            mma_bf16(d[nt], al0, al1, al2, al3, bh0, bh1);
        }
    }

    int r1 = row0 + wid * 16 + g, r2 = r1 + 8;
#pragma unroll
    for (int nt = 0; nt < 16; nt++) {
        if (r1 < NN) *(float2*)&g_xw2[(size_t)r1 * C2 + nt * 8 + c * 2] = make_float2(d[nt][0], d[nt][1]);
        if (r2 < NN) *(float2*)&g_xw2[(size_t)r2 * C2 + nt * 8 + c * 2] = make_float2(d[nt][2], d[nt][3]);
    }
#pragma unroll
    for (int h = 0; h < 8; h++) {
        float s1 = 0.f, t1 = 0.f, s2 = 0.f, t2 = 0.f;
#pragma unroll
        for (int sub = 0; sub < 2; sub++) {
            int nt = h * 2 + sub;
            int wcol = nt * 8 + c * 2;
            s1 += d[nt][0] * ws[wcol] + d[nt][1] * ws[wcol + 1];
            t1 += d[nt][0] * ws[128 + wcol] + d[nt][1] * ws[128 + wcol + 1];
            s2 += d[nt][2] * ws[wcol] + d[nt][3] * ws[wcol + 1];
            t2 += d[nt][2] * ws[128 + wcol] + d[nt][3] * ws[128 + wcol + 1];
        }
#pragma unroll
        for (int mk = 1; mk <= 2; mk <<= 1) {
            s1 += __shfl_xor_sync(0xffffffffu, s1, mk);
            t1 += __shfl_xor_sync(0xffffffffu, t1, mk);
            s2 += __shfl_xor_sync(0xffffffffu, s2, mk);
            t2 += __shfl_xor_sync(0xffffffffu, t2, mk);
        }
        if (c == 0) {
            if (r1 < NN) { g_al2s[r1 * NH + h] = s1; g_al2d[r1 * NH + h] = t1; }
            if (r2 < NN) { g_al2s[r2 * NH + h] = s2; g_al2d[r2 * NH + h] = t2; }
        }
    }
}

// ---------- GAT layer 1: raw-e smem, fused alpha write, vector LDS ---------
__global__ __launch_bounds__(256) void gat1_k(float* __restrict__ alpha_out,
                                              const float* __restrict__ b1,
                                              int alpha_rows) {
    __shared__ float s_al[8][8][SPAD];   // [warp][head][slot] raw exp(e); 272B rows
    __shared__ int   s_sr[8][MAXD];
    int w = threadIdx.x >> 5, lane = threadIdx.x & 31;
    int n = blockIdx.x * 8 + w;
    int deg = g_cur[n]; if (deg > MAXD) deg = MAXD;
    int base = n * MAXD;

    float4 d0 = *(const float4*)&g_al1d[n * NH];
    float4 d1 = *(const float4*)&g_al1d[n * NH + 4];
    float ald[8] = {d0.x, d0.y, d0.z, d0.w, d1.x, d1.y, d1.z, d1.w};

    float s[8];
#pragma unroll
    for (int h = 0; h < 8; h++) s[h] = 0.f;
    for (int i = lane; i < deg; i += 32) {
        int sr = __ldg(&g_srcs[base + i]);
        s_sr[w][i] = sr;
        float4 a0 = __ldg((const float4*)&g_al1s[sr * NH]);
        float4 a1 = __ldg((const float4*)&g_al1s[sr * NH + 4]);
        float ev[8] = {a0.x, a0.y, a0.z, a0.w, a1.x, a1.y, a1.z, a1.w};
#pragma unroll
        for (int h = 0; h < 8; h++) {
            float t = ev[h] + ald[h];
            t = t > 0.f ? t : NEG_SLOPE * t;
            t = __expf(t);
            s_al[w][h][i] = t;
            s[h] += t;
        }
    }
#pragma unroll
    for (int h = 0; h < 8; h++)
#pragma unroll
        for (int mk = 1; mk < 32; mk <<= 1)
            s[h] += __shfl_xor_sync(0xffffffffu, s[h], mk);
    float inv[8];
#pragma unroll
    for (int h = 0; h < 8; h++) inv[h] = 1.f / (s[h] + 1e-16f);
    __syncwarp();

    // alpha output: lane-strided over slots; 8 conflict-free LDS per slot
    for (int i = lane; i < deg; i += 32) {
        int eid = __ldg(&g_eid[base + i]);
        float al[8];
#pragma unroll
        for (int h = 0; h < 8; h++) al[h] = s_al[w][h][i] * inv[h];
        if (eid < alpha_rows) {
            *(float4*)&alpha_out[(size_t)eid * NH]     = make_float4(al[0], al[1], al[2], al[3]);
            *(float4*)&alpha_out[(size_t)eid * NH + 4] = make_float4(al[4], al[5], al[6], al[7]);
        }
    }

    // coalesced feature accumulation over raw e; vector LDS; inv at end
    int hme = lane >> 2;
    const float2* xb = (const float2*)g_xw1 + lane;   // + sr*32 per row
    const float* arow = &s_al[w][hme][0];
    const int*   srow = &s_sr[w][0];
    float acc0 = 0.f, acc1 = 0.f;
    int i = 0;
    for (; i + 4 <= deg; i += 4) {
        int4   s4 = *(const int4*)(srow + i);
        float4 a4 = *(const float4*)(arow + i);
        float2 v0 = __ldg(xb + s4.x * 32);
        float2 v1 = __ldg(xb + s4.y * 32);
        float2 v2 = __ldg(xb + s4.z * 32);
        float2 v3 = __ldg(xb + s4.w * 32);
        acc0 += a4.x * v0.x + a4.y * v1.x + a4.z * v2.x + a4.w * v3.x;
        acc1 += a4.x * v0.y + a4.y * v1.y + a4.z * v2.y + a4.w * v3.y;
    }
    for (; i < deg; i++) {
        int sr = srow[i];
        float a = arow[i];
        float2 v = __ldg(xb + sr * 32);
        acc0 += a * v.x;
        acc1 += a * v.y;
    }
    float iv = inv[hme];
    int f = lane * 2;
    float2 bb = __ldg((const float2*)&b1[f]);
    float v0 = acc0 * iv + bb.x, v1 = acc1 * iv + bb.y;
    v0 = v0 > 0.f ? v0 : (__expf(v0) - 1.f);   // ELU
    v1 = v1 > 0.f ? v1 : (__expf(v1) - 1.f);
    *(float2*)&g_h1[(size_t)n * C1 + f] = make_float2(v0, v1);
}

// ---------- GAT layer 2 + log_softmax: raw-e smem, vector LDS --------------
__global__ __launch_bounds__(256) void gat2_k(float* __restrict__ logp,
                                              const float* __restrict__ b2) {
    __shared__ float s_al[8][8][SPAD];
    __shared__ int   s_sr[8][MAXD];
    int w = threadIdx.x >> 5, lane = threadIdx.x & 31;
    int n = blockIdx.x * 8 + w;
    int deg = g_cur[n]; if (deg > MAXD) deg = MAXD;
    int base = n * MAXD;

    float4 d0 = *(const float4*)&g_al2d[n * NH];
    float4 d1 = *(const float4*)&g_al2d[n * NH + 4];
    float ald[8] = {d0.x, d0.y, d0.z, d0.w, d1.x, d1.y, d1.z, d1.w};

    float s[8];
#pragma unroll
    for (int h = 0; h < 8; h++) s[h] = 0.f;
    for (int i = lane; i < deg; i += 32) {
        int sr = __ldg(&g_srcs[base + i]);
        s_sr[w][i] = sr;
        float4 a0 = __ldg((const float4*)&g_al2s[sr * NH]);
        float4 a1 = __ldg((const float4*)&g_al2s[sr * NH + 4]);
        float ev[8] = {a0.x, a0.y, a0.z, a0.w, a1.x, a1.y, a1.z, a1.w};
#pragma unroll
        for (int h = 0; h < 8; h++) {
            float t = ev[h] + ald[h];
            t = t > 0.f ? t : NEG_SLOPE * t;
            t = __expf(t);
            s_al[w][h][i] = t;
            s[h] += t;
        }
    }
#pragma unroll
    for (int h = 0; h < 8; h++)
#pragma unroll
        for (int mk = 1; mk < 32; mk <<= 1)
            s[h] += __shfl_xor_sync(0xffffffffu, s[h], mk);
    float inv[8];
#pragma unroll
    for (int h = 0; h < 8; h++) inv[h] = 1.f / (s[h] + 1e-16f);
    __syncwarp();

    int hme = lane >> 2;
    const float4* xb = (const float4*)g_xw2 + lane;   // + sr*32 per row
    const float* arow = &s_al[w][hme][0];
    const int*   srow = &s_sr[w][0];
    float acc[4] = {0.f, 0.f, 0.f, 0.f};
    int i = 0;
    for (; i + 4 <= deg; i += 4) {
        int4   s4 = *(const int4*)(srow + i);
        float4 a4 = *(const float4*)(arow + i);
        float4 v0 = __ldg(xb + s4.x * 32);
        float4 v1 = __ldg(xb + s4.y * 32);
        float4 v2 = __ldg(xb + s4.z * 32);
        float4 v3 = __ldg(xb + s4.w * 32);
        acc[0] += a4.x * v0.x + a4.y * v1.x + a4.z * v2.x + a4.w * v3.x;
        acc[1] += a4.x * v0.y + a4.y * v1.y + a4.z * v2.y + a4.w * v3.y;
        acc[2] += a4.x * v0.z + a4.y * v1.z + a4.z * v2.z + a4.w * v3.z;
        acc[3] += a4.x * v0.w + a4.y * v1.w + a4.z * v2.w + a4.w * v3.w;
    }
    for (; i < deg; i++) {
        int sr = srow[i];
        float a = arow[i];
        float4 v = __ldg(xb + sr * 32);
        acc[0] += a * v.x; acc[1] += a * v.y;
        acc[2] += a * v.z; acc[3] += a * v.w;
    }
    float iv = inv[hme];
    int f = lane * 4;
    float4 bb = __ldg((const float4*)&b2[f]);
    float v[4] = {acc[0] * iv + bb.x, acc[1] * iv + bb.y,
                  acc[2] * iv + bb.z, acc[3] * iv + bb.w};

    float mx = fmaxf(fmaxf(v[0], v[1]), fmaxf(v[2], v[3]));
#pragma unroll
    for (int off = 16; off >= 1; off >>= 1)
        mx = fmaxf(mx, __shfl_xor_sync(0xffffffffu, mx, off));
    float se = 0.f;
#pragma unroll
    for (int q = 0; q < 4; q++) se += __expf(v[q] - mx);
#pragma unroll
    for (int off = 16; off >= 1; off >>= 1)
        se += __shfl_xor_sync(0xffffffffu, se, off);
    float lse = mx + __logf(se);
    *(float4*)&logp[(size_t)n * C2 + f] =
        make_float4(v[0] - lse, v[1] - lse, v[2] - lse, v[3] - lse);
}

// ---------------- launch ---------------------------------------------------
extern "C" void kernel_launch(void* const* d_in, const int* in_sizes, int n_in,
                              void* d_out, int out_size) {
    const float* x   = (const float*)d_in[0];
    const int*   ei  = (const int*)d_in[1];
    const float* W1  = (const float*)d_in[2];
    const float* a1s = (const float*)d_in[3];
    const float* a1d = (const float*)d_in[4];
    const float* b1  = (const float*)d_in[5];
    const float* W2  = (const float*)d_in[6];
    const float* a2s = (const float*)d_in[7];
    const float* a2d = (const float*)d_in[8];
    const float* b2  = (const float*)d_in[9];

    float* out   = (float*)d_out;
    float* logp  = out;                // [NN, 128]
    float* alpha = out + NN * C2;      // [E+loops, 8]
    int alpha_rows = (out_size - NN * C2) / NH;
    if (alpha_rows < 0) alpha_rows = 0;

    static cudaStream_t s_side = nullptr;
    static cudaEvent_t  ev_fork = nullptr, ev_join = nullptr;
    if (s_side == nullptr) {
        cudaStreamCreateWithFlags(&s_side, cudaStreamNonBlocking);
        cudaEventCreateWithFlags(&ev_fork, cudaEventDisableTiming);
        cudaEventCreateWithFlags(&ev_join, cudaEventDisableTiming);
        cudaFuncSetAttribute(gemm1_m, cudaFuncAttributeMaxDynamicSharedMemorySize, G1_SMEM);
        cudaFuncSetAttribute(gemm2_m, cudaFuncAttributeMaxDynamicSharedMemorySize, G2_SMEM);
    }

    // fork: padded-CSR build on side stream, concurrent with gemm1
    cudaEventRecord(ev_fork, 0);
    cudaStreamWaitEvent(s_side, ev_fork, 0);

    zero_cur_k<<<(NN / 4 + 256) / 256, 256, 0, s_side>>>();
    {
        const int nthr = EIN / 8 + (NN + 7) / 8;
        scatter_k<<<(nthr + 255) / 256, 256, 0, s_side>>>(ei);
    }
    cudaEventRecord(ev_join, s_side);

    gemm1_m<<<(NN + 127) / 128, 256, G1_SMEM>>>(x, W1, a1s, a1d);

    cudaStreamWaitEvent(0, ev_join, 0);

    gat1_k<<<NN / 8, 256>>>(alpha, b1, alpha_rows);
    gemm2_m<<<(NN + 127) / 128, 256, G2_SMEM>>>(W2, a2s, a2d);
    gat2_k<<<NN / 8, 256>>>(logp, b2);
}

// round 15
// speedup vs baseline: 1.0455x; 1.0455x over previous
#include <cuda_runtime.h>
#include <cuda_bf16.h>
#include <cstdint>

#define NN  50000
#define EIN 800000
#define FIN 256
#define C1  64       // H1*D1
#define C2  128      // H2*C
#define NH  8
#define MAXD 64      // padded CSR slots per node (Poisson(16): P(deg>64) ~ 1e-21)
#define NEG_SLOPE 0.2f

// ---------------- scratch (device globals; no allocation allowed) ----------
__device__ __align__(16) float g_xw1[NN * C1];
__device__ __align__(16) float g_al1s[NN * NH];
__device__ __align__(16) float g_al1d[NN * NH];
__device__ __align__(16) float g_h1[NN * C1];
__device__ __align__(16) float g_xw2[NN * C2];
__device__ __align__(16) float g_al2s[NN * NH];
__device__ __align__(16) float g_al2d[NN * NH];
__device__ __align__(16) int   g_cur[NN];
__device__ int   g_srcs[NN * MAXD];
__device__ int   g_eid[NN * MAXD];

// ---------------- helpers --------------------------------------------------
__device__ __forceinline__ uint32_t pkbf(float a, float b) {
    __nv_bfloat162 t = __floats2bfloat162_rn(a, b);
    return *(uint32_t*)&t;
}
__device__ __forceinline__ void mma_bf16(float* d, uint32_t a0, uint32_t a1,
                                         uint32_t a2, uint32_t a3,
                                         uint32_t b0, uint32_t b1) {
    asm volatile(
        "mma.sync.aligned.m16n8k16.row.col.f32.bf16.bf16.f32 "
        "{%0,%1,%2,%3}, {%4,%5,%6,%7}, {%8,%9}, {%0,%1,%2,%3};"
        : "+f"(d[0]), "+f"(d[1]), "+f"(d[2]), "+f"(d[3])
        : "r"(a0), "r"(a1), "r"(a2), "r"(a3), "r"(b0), "r"(b1));
}

// ---------------- CSR build (padded, no scan) ------------------------------
__global__ void zero_cur_k() {
    int i = blockIdx.x * blockDim.x + threadIdx.x;
    if (i * 4 + 3 < NN) *(int4*)&g_cur[i * 4] = make_int4(0, 0, 0, 0);
    else for (int n = i * 4; n < NN; n++) g_cur[n] = 0;
}

__global__ void scatter_k(const int* __restrict__ ei) {
    const int NE8 = EIN / 8;
    int t = blockIdx.x * blockDim.x + threadIdx.x;
    if (t < NE8) {
        int e = t * 8;
        int4 s0 = *(const int4*)&ei[e];
        int4 s1 = *(const int4*)&ei[e + 4];
        int4 d0 = *(const int4*)&ei[EIN + e];
        int4 d1 = *(const int4*)&ei[EIN + e + 4];
        int p;
        p = atomicAdd(&g_cur[d0.x], 1); if (p < MAXD) { g_srcs[d0.x * MAXD + p] = s0.x; g_eid[d0.x * MAXD + p] = e; }
        p = atomicAdd(&g_cur[d0.y], 1); if (p < MAXD) { g_srcs[d0.y * MAXD + p] = s0.y; g_eid[d0.y * MAXD + p] = e + 1; }
        p = atomicAdd(&g_cur[d0.z], 1); if (p < MAXD) { g_srcs[d0.z * MAXD + p] = s0.z; g_eid[d0.z * MAXD + p] = e + 2; }
        p = atomicAdd(&g_cur[d0.w], 1); if (p < MAXD) { g_srcs[d0.w * MAXD + p] = s0.w; g_eid[d0.w * MAXD + p] = e + 3; }
        p = atomicAdd(&g_cur[d1.x], 1); if (p < MAXD) { g_srcs[d1.x * MAXD + p] = s1.x; g_eid[d1.x * MAXD + p] = e + 4; }
        p = atomicAdd(&g_cur[d1.y], 1); if (p < MAXD) { g_srcs[d1.y * MAXD + p] = s1.y; g_eid[d1.y * MAXD + p] = e + 5; }
        p = atomicAdd(&g_cur[d1.z], 1); if (p < MAXD) { g_srcs[d1.z * MAXD + p] = s1.z; g_eid[d1.z * MAXD + p] = e + 6; }
        p = atomicAdd(&g_cur[d1.w], 1); if (p < MAXD) { g_srcs[d1.w * MAXD + p] = s1.w; g_eid[d1.w * MAXD + p] = e + 7; }
    } else {
        int n0 = (t - NE8) * 8;
#pragma unroll
        for (int k = 0; k < 8; k++) {
            int n = n0 + k;
            if (n < NN) {
                int p = atomicAdd(&g_cur[n], 1);
                if (p < MAXD) { g_srcs[n * MAXD + p] = n; g_eid[n * MAXD + p] = EIN + n; }
            }
        }
    }
}

// ============ GEMM1 (mma.sync bf16x3): xw1 = x @ W1, fused al1 =============
#define S1ROW 144
#define G1_WS  0
#define G1_AHI 512
#define G1_ALO (G1_AHI + 128 * S1ROW)
#define G1_BHI (G1_ALO + 128 * S1ROW)
#define G1_BLO (G1_BHI + 64 * S1ROW)
#define G1_SMEM (G1_BLO + 64 * S1ROW)

__global__ __launch_bounds__(256) void gemm1_m(
    const float* __restrict__ A, const float* __restrict__ W,
    const float* __restrict__ a1s, const float* __restrict__ a1d) {
    extern __shared__ char sm[];
    float* ws = (float*)(sm + G1_WS);
    int tid = threadIdx.x, wid = tid >> 5, lid = tid & 31;
    int g = lid >> 2, c = lid & 3;
    int row0 = blockIdx.x * 128;

    if (tid < 64) ws[tid] = a1s[tid];
    else if (tid < 128) ws[tid] = a1d[tid - 64];

    float d[8][4];
#pragma unroll
    for (int nt = 0; nt < 8; nt++)
#pragma unroll
        for (int q = 0; q < 4; q++) d[nt][q] = 0.f;

    for (int kc = 0; kc < 4; kc++) {
        if (kc) __syncthreads();
#pragma unroll
        for (int it = 0; it < 8; it++) {
            int idx = tid + it * 256;
            int r = idx >> 4, k = (idx & 15) << 2;
            int gr = row0 + r;
            float4 v = (gr < NN) ? *(const float4*)&A[(size_t)gr * FIN + kc * 64 + k]
                                 : make_float4(0.f, 0.f, 0.f, 0.f);
            uint32_t h0 = pkbf(v.x, v.y), h1 = pkbf(v.z, v.w);
            uint32_t l0 = pkbf(v.x - __bfloat162float(__float2bfloat16(v.x)),
                               v.y - __bfloat162float(__float2bfloat16(v.y)));
            uint32_t l1 = pkbf(v.z - __bfloat162float(__float2bfloat16(v.z)),
                               v.w - __bfloat162float(__float2bfloat16(v.w)));
            *(uint2*)(sm + G1_AHI + r * S1ROW + k * 2) = make_uint2(h0, h1);
            *(uint2*)(sm + G1_ALO + r * S1ROW + k * 2) = make_uint2(l0, l1);
        }
#pragma unroll
        for (int it = 0; it < 4; it++) {
            int idx = tid + it * 256;
            int n = idx & 63, k = (idx >> 6) << 2;
            float v0 = W[(kc * 64 + k) * 64 + n];
            float v1 = W[(kc * 64 + k + 1) * 64 + n];
            float v2 = W[(kc * 64 + k + 2) * 64 + n];
            float v3 = W[(kc * 64 + k + 3) * 64 + n];
            uint32_t h0 = pkbf(v0, v1), h1 = pkbf(v2, v3);
            uint32_t l0 = pkbf(v0 - __bfloat162float(__float2bfloat16(v0)),
                               v1 - __bfloat162float(__float2bfloat16(v1)));
            uint32_t l1 = pkbf(v2 - __bfloat162float(__float2bfloat16(v2)),
                               v3 - __bfloat162float(__float2bfloat16(v3)));
            *(uint2*)(sm + G1_BHI + n * S1ROW + k * 2) = make_uint2(h0, h1);
            *(uint2*)(sm + G1_BLO + n * S1ROW + k * 2) = make_uint2(l0, l1);
        }
        __syncthreads();

#pragma unroll
        for (int ks = 0; ks < 4; ks++) {
            int k0 = ks * 16;
            const char* pah = sm + G1_AHI + (wid * 16 + g) * S1ROW + (k0 + c * 2) * 2;
            const char* pal = sm + G1_ALO + (wid * 16 + g) * S1ROW + (k0 + c * 2) * 2;
            uint32_t ah0 = *(const uint32_t*)(pah);
            uint32_t ah1 = *(const uint32_t*)(pah + 8 * S1ROW);
            uint32_t ah2 = *(const uint32_t*)(pah + 16);
            uint32_t ah3 = *(const uint32_t*)(pah + 8 * S1ROW + 16);
            uint32_t al0 = *(const uint32_t*)(pal);
            uint32_t al1 = *(const uint32_t*)(pal + 8 * S1ROW);
            uint32_t al2 = *(const uint32_t*)(pal + 16);
            uint32_t al3 = *(const uint32_t*)(pal + 8 * S1ROW + 16);
#pragma unroll
            for (int nt = 0; nt < 8; nt++) {
                const char* pbh = sm + G1_BHI + (nt * 8 + g) * S1ROW + (k0 + c * 2) * 2;
                const char* pbl = sm + G1_BLO + (nt * 8 + g) * S1ROW + (k0 + c * 2) * 2;
                uint32_t bh0 = *(const uint32_t*)(pbh);
                uint32_t bh1 = *(const uint32_t*)(pbh + 16);
                uint32_t bl0 = *(const uint32_t*)(pbl);
                uint32_t bl1 = *(const uint32_t*)(pbl + 16);
                mma_bf16(d[nt], ah0, ah1, ah2, ah3, bh0, bh1);
                mma_bf16(d[nt], ah0, ah1, ah2, ah3, bl0, bl1);
                mma_bf16(d[nt], al0, al1, al2, al3, bh0, bh1);
            }
        }
    }

    int r1 = row0 + wid * 16 + g, r2 = r1 + 8;
#pragma unroll
    for (int nt = 0; nt < 8; nt++) {
        if (r1 < NN) *(float2*)&g_xw1[(size_t)r1 * C1 + nt * 8 + c * 2] = make_float2(d[nt][0], d[nt][1]);
        if (r2 < NN) *(float2*)&g_xw1[(size_t)r2 * C1 + nt * 8 + c * 2] = make_float2(d[nt][2], d[nt][3]);
    }
#pragma unroll
    for (int h = 0; h < 8; h++) {
        int wcol = h * 8 + c * 2;
        float s1 = d[h][0] * ws[wcol] + d[h][1] * ws[wcol + 1];
        float t1 = d[h][0] * ws[64 + wcol] + d[h][1] * ws[64 + wcol + 1];
        float s2 = d[h][2] * ws[wcol] + d[h][3] * ws[wcol + 1];
        float t2 = d[h][2] * ws[64 + wcol] + d[h][3] * ws[64 + wcol + 1];
#pragma unroll
        for (int mk = 1; mk <= 2; mk <<= 1) {
            s1 += __shfl_xor_sync(0xffffffffu, s1, mk);
            t1 += __shfl_xor_sync(0xffffffffu, t1, mk);
            s2 += __shfl_xor_sync(0xffffffffu, s2, mk);
            t2 += __shfl_xor_sync(0xffffffffu, t2, mk);
        }
        if (c == 0) {
            if (r1 < NN) { g_al1s[r1 * NH + h] = s1; g_al1d[r1 * NH + h] = t1; }
            if (r2 < NN) { g_al1s[r2 * NH + h] = s2; g_al1d[r2 * NH + h] = t2; }
        }
    }
}

// ============ GEMM2 (mma.sync bf16x3): xw2 = h1 @ W2, fused al2 =============
#define G2_WS  0
#define G2_AHI 1024
#define G2_ALO (G2_AHI + 128 * S1ROW)
#define G2_BHI (G2_ALO + 128 * S1ROW)
#define G2_BLO (G2_BHI + 128 * S1ROW)
#define G2_SMEM (G2_BLO + 128 * S1ROW)

__global__ __launch_bounds__(256) void gemm2_m(
    const float* __restrict__ W,
    const float* __restrict__ a2s, const float* __restrict__ a2d) {
    extern __shared__ char sm[];
    float* ws = (float*)(sm + G2_WS);
    int tid = threadIdx.x, wid = tid >> 5, lid = tid & 31;
    int g = lid >> 2, c = lid & 3;
    int row0 = blockIdx.x * 128;

    if (tid < 128) ws[tid] = a2s[tid];
    else ws[tid] = a2d[tid - 128];

#pragma unroll
    for (int it = 0; it < 8; it++) {
        int idx = tid + it * 256;
        int r = idx >> 4, k = (idx & 15) << 2;
        int gr = row0 + r;
        float4 v = (gr < NN) ? *(const float4*)&g_h1[(size_t)gr * C1 + k]
                             : make_float4(0.f, 0.f, 0.f, 0.f);
        uint32_t h0 = pkbf(v.x, v.y), h1 = pkbf(v.z, v.w);
        uint32_t l0 = pkbf(v.x - __bfloat162float(__float2bfloat16(v.x)),
                           v.y - __bfloat162float(__float2bfloat16(v.y)));
        uint32_t l1 = pkbf(v.z - __bfloat162float(__float2bfloat16(v.z)),
                           v.w - __bfloat162float(__float2bfloat16(v.w)));
        *(uint2*)(sm + G2_AHI + r * S1ROW + k * 2) = make_uint2(h0, h1);
        *(uint2*)(sm + G2_ALO + r * S1ROW + k * 2) = make_uint2(l0, l1);
    }
#pragma unroll
    for (int it = 0; it < 8; it++) {
        int idx = tid + it * 256;
        int n = idx & 127, k = (idx >> 7) << 2;
        float v0 = W[(k) * 128 + n];
        float v1 = W[(k + 1) * 128 + n];
        float v2 = W[(k + 2) * 128 + n];
        float v3 = W[(k + 3) * 128 + n];
        uint32_t h0 = pkbf(v0, v1), h1 = pkbf(v2, v3);
        uint32_t l0 = pkbf(v0 - __bfloat162float(__float2bfloat16(v0)),
                           v1 - __bfloat162float(__float2bfloat16(v1)));
        uint32_t l1 = pkbf(v2 - __bfloat162float(__float2bfloat16(v2)),
                           v3 - __bfloat162float(__float2bfloat16(v3)));
        *(uint2*)(sm + G2_BHI + n * S1ROW + k * 2) = make_uint2(h0, h1);
        *(uint2*)(sm + G2_BLO + n * S1ROW + k * 2) = make_uint2(l0, l1);
    }
    __syncthreads();

    float d[16][4];
#pragma unroll
    for (int nt = 0; nt < 16; nt++)
#pragma unroll
        for (int q = 0; q < 4; q++) d[nt][q] = 0.f;

#pragma unroll
    for (int ks = 0; ks < 4; ks++) {
        int k0 = ks * 16;
        const char* pah = sm + G2_AHI + (wid * 16 + g) * S1ROW + (k0 + c * 2) * 2;
        const char* pal = sm + G2_ALO + (wid * 16 + g) * S1ROW + (k0 + c * 2) * 2;
        uint32_t ah0 = *(const uint32_t*)(pah);
        uint32_t ah1 = *(const uint32_t*)(pah + 8 * S1ROW);
        uint32_t ah2 = *(const uint32_t*)(pah + 16);
        uint32_t ah3 = *(const uint32_t*)(pah + 8 * S1ROW + 16);
        uint32_t al0 = *(const uint32_t*)(pal);
        uint32_t al1 = *(const uint32_t*)(pal + 8 * S1ROW);
        uint32_t al2 = *(const uint32_t*)(pal + 16);
        uint32_t al3 = *(const uint32_t*)(pal + 8 * S1ROW + 16);
#pragma unroll
        for (int nt = 0; nt < 16; nt++) {
            const char* pbh = sm + G2_BHI + (nt * 8 + g) * S1ROW + (k0 + c * 2) * 2;
            const char* pbl = sm + G2_BLO + (nt * 8 + g) * S1ROW + (k0 + c * 2) * 2;
            uint32_t bh0 = *(const uint32_t*)(pbh);
            uint32_t bh1 = *(const uint32_t*)(pbh + 16);
            uint32_t bl0 = *(const uint32_t*)(pbl);
            uint32_t bl1 = *(const uint32_t*)(pbl + 16);
            mma_bf16(d[nt], ah0, ah1, ah2, ah3, bh0, bh1);
            mma_bf16(d[nt], ah0, ah1, ah2, ah3, bl0, bl1);
            mma_bf16(d[nt], al0, al1, al2, al3, bh0, bh1);
        }
    }

    int r1 = row0 + wid * 16 + g, r2 = r1 + 8;
#pragma unroll
    for (int nt = 0; nt < 16; nt++) {
        if (r1 < NN) *(float2*)&g_xw2[(size_t)r1 * C2 + nt * 8 + c * 2] = make_float2(d[nt][0], d[nt][1]);
        if (r2 < NN) *(float2*)&g_xw2[(size_t)r2 * C2 + nt * 8 + c * 2] = make_float2(d[nt][2], d[nt][3]);
    }
#pragma unroll
    for (int h = 0; h < 8; h++) {
        float s1 = 0.f, t1 = 0.f, s2 = 0.f, t2 = 0.f;
#pragma unroll
        for (int sub = 0; sub < 2; sub++) {
            int nt = h * 2 + sub;
            int wcol = nt * 8 + c * 2;
            s1 += d[nt][0] * ws[wcol] + d[nt][1] * ws[wcol + 1];
            t1 += d[nt][0] * ws[128 + wcol] + d[nt][1] * ws[128 + wcol + 1];
            s2 += d[nt][2] * ws[wcol] + d[nt][3] * ws[wcol + 1];
            t2 += d[nt][2] * ws[128 + wcol] + d[nt][3] * ws[128 + wcol + 1];
        }
#pragma unroll
        for (int mk = 1; mk <= 2; mk <<= 1) {
            s1 += __shfl_xor_sync(0xffffffffu, s1, mk);
            t1 += __shfl_xor_sync(0xffffffffu, t1, mk);
            s2 += __shfl_xor_sync(0xffffffffu, s2, mk);
            t2 += __shfl_xor_sync(0xffffffffu, t2, mk);
        }
        if (c == 0) {
            if (r1 < NN) { g_al2s[r1 * NH + h] = s1; g_al2d[r1 * NH + h] = t1; }
            if (r2 < NN) { g_al2s[r2 * NH + h] = s2; g_al2d[r2 * NH + h] = t2; }
        }
    }
}

// ---------- GAT layer 1 (R12 structure): one warp per node, no-max ---------
__global__ __launch_bounds__(256) void gat1_k(float* __restrict__ alpha_out,
                                              const float* __restrict__ b1,
                                              int alpha_rows) {
    __shared__ float s_al[8][8][MAXD + 2];   // [warp][head][slot]
    __shared__ int   s_sr[8][MAXD];
    int w = threadIdx.x >> 5, lane = threadIdx.x & 31;
    int n = blockIdx.x * 8 + w;
    int deg = g_cur[n]; if (deg > MAXD) deg = MAXD;
    int base = n * MAXD;

    float4 d0 = *(const float4*)&g_al1d[n * NH];
    float4 d1 = *(const float4*)&g_al1d[n * NH + 4];
    float ald[8] = {d0.x, d0.y, d0.z, d0.w, d1.x, d1.y, d1.z, d1.w};

    // single pass: e = exp(leaky(logit)) in registers, accumulate s
    float e[2][8];
    int   srt[2];
    float s[8];
#pragma unroll
    for (int h = 0; h < 8; h++) s[h] = 0.f;
    int ns = 0;
    for (int i = lane; i < deg; i += 32) {
        int sr = __ldg(&g_srcs[base + i]);
        srt[ns] = sr;
        float4 a0 = __ldg((const float4*)&g_al1s[sr * NH]);
        float4 a1 = __ldg((const float4*)&g_al1s[sr * NH + 4]);
        float ev[8] = {a0.x, a0.y, a0.z, a0.w, a1.x, a1.y, a1.z, a1.w};
#pragma unroll
        for (int h = 0; h < 8; h++) {
            float t = ev[h] + ald[h];
            t = t > 0.f ? t : NEG_SLOPE * t;
            t = __expf(t);
            e[ns][h] = t;
            s[h] += t;
        }
        ns++;
    }
#pragma unroll
    for (int h = 0; h < 8; h++)
#pragma unroll
        for (int mk = 1; mk < 32; mk <<= 1)
            s[h] += __shfl_xor_sync(0xffffffffu, s[h], mk);
    float inv[8];
#pragma unroll
    for (int h = 0; h < 8; h++) inv[h] = 1.f / (s[h] + 1e-16f);

    // normalize from registers; park alpha + src in smem; write alpha out
    {
        int t = 0;
        for (int i = lane; i < deg; i += 32, t++) {
            float al[8];
#pragma unroll
            for (int h = 0; h < 8; h++) al[h] = e[t][h] * inv[h];
            s_sr[w][i] = srt[t];
#pragma unroll
            for (int h = 0; h < 8; h++) s_al[w][h][i] = al[h];
            int eid = __ldg(&g_eid[base + i]);
            if (eid < alpha_rows) {
                *(float4*)&alpha_out[(size_t)eid * NH]     = make_float4(al[0], al[1], al[2], al[3]);
                *(float4*)&alpha_out[(size_t)eid * NH + 4] = make_float4(al[4], al[5], al[6], al[7]);
            }
        }
    }
    __syncwarp();

    // coalesced feature accumulation, unrolled x4
    int hme = lane >> 2;
    const float2* xb = (const float2*)g_xw1 + lane;   // + sr*32 per row
    float acc0 = 0.f, acc1 = 0.f;
    int i = 0;
    for (; i + 4 <= deg; i += 4) {
        int sr0 = s_sr[w][i],     sr1 = s_sr[w][i + 1];
        int sr2 = s_sr[w][i + 2], sr3 = s_sr[w][i + 3];
        float a0 = s_al[w][hme][i],     a1 = s_al[w][hme][i + 1];
        float a2 = s_al[w][hme][i + 2], a3 = s_al[w][hme][i + 3];
        float2 v0 = __ldg(xb + sr0 * 32);
        float2 v1 = __ldg(xb + sr1 * 32);
        float2 v2 = __ldg(xb + sr2 * 32);
        float2 v3 = __ldg(xb + sr3 * 32);
        acc0 += a0 * v0.x + a1 * v1.x + a2 * v2.x + a3 * v3.x;
        acc1 += a0 * v0.y + a1 * v1.y + a2 * v2.y + a3 * v3.y;
    }
    for (; i < deg; i++) {
        int sr = s_sr[w][i];
        float a = s_al[w][hme][i];
        float2 v = __ldg(xb + sr * 32);
        acc0 += a * v.x;
        acc1 += a * v.y;
    }
    int f = lane * 2;
    float2 bb = __ldg((const float2*)&b1[f]);
    float v0 = acc0 + bb.x, v1 = acc1 + bb.y;
    v0 = v0 > 0.f ? v0 : (__expf(v0) - 1.f);   // ELU
    v1 = v1 > 0.f ? v1 : (__expf(v1) - 1.f);
    *(float2*)&g_h1[(size_t)n * C1 + f] = make_float2(v0, v1);
}

// ---------- GAT layer 2 (R13 structure): raw-e smem, inv at end ------------
__global__ __launch_bounds__(256) void gat2_k(float* __restrict__ logp,
                                              const float* __restrict__ b2) {
    __shared__ float s_al[8][8][MAXD + 2];
    __shared__ int   s_sr[8][MAXD];
    int w = threadIdx.x >> 5, lane = threadIdx.x & 31;
    int n = blockIdx.x * 8 + w;
    int deg = g_cur[n]; if (deg > MAXD) deg = MAXD;
    int base = n * MAXD;

    float4 d0 = *(const float4*)&g_al2d[n * NH];
    float4 d1 = *(const float4*)&g_al2d[n * NH + 4];
    float ald[8] = {d0.x, d0.y, d0.z, d0.w, d1.x, d1.y, d1.z, d1.w};

    float s[8];
#pragma unroll
    for (int h = 0; h < 8; h++) s[h] = 0.f;
    for (int i = lane; i < deg; i += 32) {
        int sr = __ldg(&g_srcs[base + i]);
        s_sr[w][i] = sr;
        float4 a0 = __ldg((const float4*)&g_al2s[sr * NH]);
        float4 a1 = __ldg((const float4*)&g_al2s[sr * NH + 4]);
        float ev[8] = {a0.x, a0.y, a0.z, a0.w, a1.x, a1.y, a1.z, a1.w};
#pragma unroll
        for (int h = 0; h < 8; h++) {
            float t = ev[h] + ald[h];
            t = t > 0.f ? t : NEG_SLOPE * t;
            t = __expf(t);
            s_al[w][h][i] = t;
            s[h] += t;
        }
    }
#pragma unroll
    for (int h = 0; h < 8; h++)
#pragma unroll
        for (int mk = 1; mk < 32; mk <<= 1)
            s[h] += __shfl_xor_sync(0xffffffffu, s[h], mk);
    float inv[8];
#pragma unroll
    for (int h = 0; h < 8; h++) inv[h] = 1.f / (s[h] + 1e-16f);
    __syncwarp();

    int hme = lane >> 2;
    const float4* xb = (const float4*)g_xw2 + lane;   // + sr*32 per row
    float acc[4] = {0.f, 0.f, 0.f, 0.f};
    int i = 0;
    for (; i + 4 <= deg; i += 4) {
        int sr0 = s_sr[w][i],     sr1 = s_sr[w][i + 1];
        int sr2 = s_sr[w][i + 2], sr3 = s_sr[w][i + 3];
        float a0 = s_al[w][hme][i],     a1 = s_al[w][hme][i + 1];
        float a2 = s_al[w][hme][i + 2], a3 = s_al[w][hme][i + 3];
        float4 v0 = __ldg(xb + sr0 * 32);
        float4 v1 = __ldg(xb + sr1 * 32);
        float4 v2 = __ldg(xb + sr2 * 32);
        float4 v3 = __ldg(xb + sr3 * 32);
        acc[0] += a0 * v0.x + a1 * v1.x + a2 * v2.x + a3 * v3.x;
        acc[1] += a0 * v0.y + a1 * v1.y + a2 * v2.y + a3 * v3.y;
        acc[2] += a0 * v0.z + a1 * v1.z + a2 * v2.z + a3 * v3.z;
        acc[3] += a0 * v0.w + a1 * v1.w + a2 * v2.w + a3 * v3.w;
    }
    for (; i < deg; i++) {
        int sr = s_sr[w][i];
        float a = s_al[w][hme][i];
        float4 v = __ldg(xb + sr * 32);
        acc[0] += a * v.x; acc[1] += a * v.y;
        acc[2] += a * v.z; acc[3] += a * v.w;
    }
    float iv = inv[hme];
    int f = lane * 4;
    float4 bb = __ldg((const float4*)&b2[f]);
    float v[4] = {acc[0] * iv + bb.x, acc[1] * iv + bb.y,
                  acc[2] * iv + bb.z, acc[3] * iv + bb.w};

    float mx = fmaxf(fmaxf(v[0], v[1]), fmaxf(v[2], v[3]));
#pragma unroll
    for (int off = 16; off >= 1; off >>= 1)
        mx = fmaxf(mx, __shfl_xor_sync(0xffffffffu, mx, off));
    float se = 0.f;
#pragma unroll
    for (int q = 0; q < 4; q++) se += __expf(v[q] - mx);
#pragma unroll
    for (int off = 16; off >= 1; off >>= 1)
        se += __shfl_xor_sync(0xffffffffu, se, off);
    float lse = mx + __logf(se);
    *(float4*)&logp[(size_t)n * C2 + f] =
        make_float4(v[0] - lse, v[1] - lse, v[2] - lse, v[3] - lse);
}

// ---------------- launch ---------------------------------------------------
extern "C" void kernel_launch(void* const* d_in, const int* in_sizes, int n_in,
                              void* d_out, int out_size) {
    const float* x   = (const float*)d_in[0];
    const int*   ei  = (const int*)d_in[1];
    const float* W1  = (const float*)d_in[2];
    const float* a1s = (const float*)d_in[3];
    const float* a1d = (const float*)d_in[4];
    const float* b1  = (const float*)d_in[5];
    const float* W2  = (const float*)d_in[6];
    const float* a2s = (const float*)d_in[7];
    const float* a2d = (const float*)d_in[8];
    const float* b2  = (const float*)d_in[9];

    float* out   = (float*)d_out;
    float* logp  = out;                // [NN, 128]
    float* alpha = out + NN * C2;      // [E+loops, 8]
    int alpha_rows = (out_size - NN * C2) / NH;
    if (alpha_rows < 0) alpha_rows = 0;

    static cudaStream_t s_side = nullptr;
    static cudaEvent_t  ev_fork = nullptr, ev_join = nullptr;
    if (s_side == nullptr) {
        cudaStreamCreateWithFlags(&s_side, cudaStreamNonBlocking);
        cudaEventCreateWithFlags(&ev_fork, cudaEventDisableTiming);
        cudaEventCreateWithFlags(&ev_join, cudaEventDisableTiming);
        cudaFuncSetAttribute(gemm1_m, cudaFuncAttributeMaxDynamicSharedMemorySize, G1_SMEM);
        cudaFuncSetAttribute(gemm2_m, cudaFuncAttributeMaxDynamicSharedMemorySize, G2_SMEM);
    }

    // fork: padded-CSR build on side stream, concurrent with gemm1
    cudaEventRecord(ev_fork, 0);
    cudaStreamWaitEvent(s_side, ev_fork, 0);

    zero_cur_k<<<(NN / 4 + 256) / 256, 256, 0, s_side>>>();
    {
        const int nthr = EIN / 8 + (NN + 7) / 8;
        scatter_k<<<(nthr + 255) / 256, 256, 0, s_side>>>(ei);
    }
    cudaEventRecord(ev_join, s_side);

    gemm1_m<<<(NN + 127) / 128, 256, G1_SMEM>>>(x, W1, a1s, a1d);

    cudaStreamWaitEvent(0, ev_join, 0);

    gat1_k<<<NN / 8, 256>>>(alpha, b1, alpha_rows);
    gemm2_m<<<(NN + 127) / 128, 256, G2_SMEM>>>(W2, a2s, a2d);
    gat2_k<<<NN / 8, 256>>>(logp, b2);
}

// round 16
// speedup vs baseline: 1.0947x; 1.0470x over previous
#include <cuda_runtime.h>
#include <cuda_bf16.h>
#include <cstdint>

#define NN  50000
#define EIN 800000
#define FIN 256
#define C1  64       // H1*D1
#define C2  128      // H2*C
#define NH  8
#define MAXD 64      // padded CSR slots per node (Poisson(16): P(deg>64) ~ 1e-21)
#define NEG_SLOPE 0.2f

// ---------------- scratch (device globals; no allocation allowed) ----------
__device__ __align__(16) float g_xw1[NN * C1];
__device__ __align__(16) float g_al1s[NN * NH];
__device__ __align__(16) float g_al1d[NN * NH];
__device__ __align__(16) float g_h1[NN * C1];
__device__ __align__(16) float g_xw2[NN * C2];
__device__ __align__(16) float g_al2s[NN * NH];
__device__ __align__(16) float g_al2d[NN * NH];
__device__ __align__(16) int   g_cur[NN];
__device__ int   g_srcs[NN * MAXD];
__device__ int   g_eid[NN * MAXD];

// ---------------- helpers --------------------------------------------------
__device__ __forceinline__ uint32_t pkbf(float a, float b) {
    __nv_bfloat162 t = __floats2bfloat162_rn(a, b);
    return *(uint32_t*)&t;
}
__device__ __forceinline__ void mma_bf16(float* d, uint32_t a0, uint32_t a1,
                                         uint32_t a2, uint32_t a3,
                                         uint32_t b0, uint32_t b1) {
    asm volatile(
        "mma.sync.aligned.m16n8k16.row.col.f32.bf16.bf16.f32 "
        "{%0,%1,%2,%3}, {%4,%5,%6,%7}, {%8,%9}, {%0,%1,%2,%3};"
        : "+f"(d[0]), "+f"(d[1]), "+f"(d[2]), "+f"(d[3])
        : "r"(a0), "r"(a1), "r"(a2), "r"(a3), "r"(b0), "r"(b1));
}

// ---------------- CSR build (padded, no scan) ------------------------------
__global__ void zero_cur_k() {
    int i = blockIdx.x * blockDim.x + threadIdx.x;
    if (i * 4 + 3 < NN) *(int4*)&g_cur[i * 4] = make_int4(0, 0, 0, 0);
    else for (int n = i * 4; n < NN; n++) g_cur[n] = 0;
}

__global__ void scatter_k(const int* __restrict__ ei) {
    const int NE8 = EIN / 8;
    int t = blockIdx.x * blockDim.x + threadIdx.x;
    if (t < NE8) {
        int e = t * 8;
        int4 s0 = *(const int4*)&ei[e];
        int4 s1 = *(const int4*)&ei[e + 4];
        int4 d0 = *(const int4*)&ei[EIN + e];
        int4 d1 = *(const int4*)&ei[EIN + e + 4];
        int p;
        p = atomicAdd(&g_cur[d0.x], 1); if (p < MAXD) { g_srcs[d0.x * MAXD + p] = s0.x; g_eid[d0.x * MAXD + p] = e; }
        p = atomicAdd(&g_cur[d0.y], 1); if (p < MAXD) { g_srcs[d0.y * MAXD + p] = s0.y; g_eid[d0.y * MAXD + p] = e + 1; }
        p = atomicAdd(&g_cur[d0.z], 1); if (p < MAXD) { g_srcs[d0.z * MAXD + p] = s0.z; g_eid[d0.z * MAXD + p] = e + 2; }
        p = atomicAdd(&g_cur[d0.w], 1); if (p < MAXD) { g_srcs[d0.w * MAXD + p] = s0.w; g_eid[d0.w * MAXD + p] = e + 3; }
        p = atomicAdd(&g_cur[d1.x], 1); if (p < MAXD) { g_srcs[d1.x * MAXD + p] = s1.x; g_eid[d1.x * MAXD + p] = e + 4; }
        p = atomicAdd(&g_cur[d1.y], 1); if (p < MAXD) { g_srcs[d1.y * MAXD + p] = s1.y; g_eid[d1.y * MAXD + p] = e + 5; }
        p = atomicAdd(&g_cur[d1.z], 1); if (p < MAXD) { g_srcs[d1.z * MAXD + p] = s1.z; g_eid[d1.z * MAXD + p] = e + 6; }
        p = atomicAdd(&g_cur[d1.w], 1); if (p < MAXD) { g_srcs[d1.w * MAXD + p] = s1.w; g_eid[d1.w * MAXD + p] = e + 7; }
    } else {
        int n0 = (t - NE8) * 8;
#pragma unroll
        for (int k = 0; k < 8; k++) {
            int n = n0 + k;
            if (n < NN) {
                int p = atomicAdd(&g_cur[n], 1);
                if (p < MAXD) { g_srcs[n * MAXD + p] = n; g_eid[n * MAXD + p] = EIN + n; }
            }
        }
    }
}

// ============ GEMM1 (mma.sync bf16x3): xw1 = x @ W1, fused al1 =============
#define S1ROW 144
#define G1_WS  0
#define G1_AHI 512
#define G1_ALO (G1_AHI + 128 * S1ROW)
#define G1_BHI (G1_ALO + 128 * S1ROW)
#define G1_BLO (G1_BHI + 64 * S1ROW)
#define G1_SMEM (G1_BLO + 64 * S1ROW)

__global__ __launch_bounds__(256) void gemm1_m(
    const float* __restrict__ A, const float* __restrict__ W,
    const float* __restrict__ a1s, const float* __restrict__ a1d) {
    extern __shared__ char sm[];
    float* ws = (float*)(sm + G1_WS);
    int tid = threadIdx.x, wid = tid >> 5, lid = tid & 31;
    int g = lid >> 2, c = lid & 3;
    int row0 = blockIdx.x * 128;

    if (tid < 64) ws[tid] = a1s[tid];
    else if (tid < 128) ws[tid] = a1d[tid - 64];

    float d[8][4];
#pragma unroll
    for (int nt = 0; nt < 8; nt++)
#pragma unroll
        for (int q = 0; q < 4; q++) d[nt][q] = 0.f;

    for (int kc = 0; kc < 4; kc++) {
        if (kc) __syncthreads();
#pragma unroll
        for (int it = 0; it < 8; it++) {
            int idx = tid + it * 256;
            int r = idx >> 4, k = (idx & 15) << 2;
            int gr = row0 + r;
            float4 v = (gr < NN) ? *(const float4*)&A[(size_t)gr * FIN + kc * 64 + k]
                                 : make_float4(0.f, 0.f, 0.f, 0.f);
            uint32_t h0 = pkbf(v.x, v.y), h1 = pkbf(v.z, v.w);
            uint32_t l0 = pkbf(v.x - __bfloat162float(__float2bfloat16(v.x)),
                               v.y - __bfloat162float(__float2bfloat16(v.y)));
            uint32_t l1 = pkbf(v.z - __bfloat162float(__float2bfloat16(v.z)),
                               v.w - __bfloat162float(__float2bfloat16(v.w)));
            *(uint2*)(sm + G1_AHI + r * S1ROW + k * 2) = make_uint2(h0, h1);
            *(uint2*)(sm + G1_ALO + r * S1ROW + k * 2) = make_uint2(l0, l1);
        }
#pragma unroll
        for (int it = 0; it < 4; it++) {
            int idx = tid + it * 256;
            int n = idx & 63, k = (idx >> 6) << 2;
            float v0 = W[(kc * 64 + k) * 64 + n];
            float v1 = W[(kc * 64 + k + 1) * 64 + n];
            float v2 = W[(kc * 64 + k + 2) * 64 + n];
            float v3 = W[(kc * 64 + k + 3) * 64 + n];
            uint32_t h0 = pkbf(v0, v1), h1 = pkbf(v2, v3);
            uint32_t l0 = pkbf(v0 - __bfloat162float(__float2bfloat16(v0)),
                               v1 - __bfloat162float(__float2bfloat16(v1)));
            uint32_t l1 = pkbf(v2 - __bfloat162float(__float2bfloat16(v2)),
                               v3 - __bfloat162float(__float2bfloat16(v3)));
            *(uint2*)(sm + G1_BHI + n * S1ROW + k * 2) = make_uint2(h0, h1);
            *(uint2*)(sm + G1_BLO + n * S1ROW + k * 2) = make_uint2(l0, l1);
        }
        __syncthreads();

#pragma unroll
        for (int ks = 0; ks < 4; ks++) {
            int k0 = ks * 16;
            const char* pah = sm + G1_AHI + (wid * 16 + g) * S1ROW + (k0 + c * 2) * 2;
            const char* pal = sm + G1_ALO + (wid * 16 + g) * S1ROW + (k0 + c * 2) * 2;
            uint32_t ah0 = *(const uint32_t*)(pah);
            uint32_t ah1 = *(const uint32_t*)(pah + 8 * S1ROW);
            uint32_t ah2 = *(const uint32_t*)(pah + 16);
            uint32_t ah3 = *(const uint32_t*)(pah + 8 * S1ROW + 16);
            uint32_t al0 = *(const uint32_t*)(pal);
            uint32_t al1 = *(const uint32_t*)(pal + 8 * S1ROW);
            uint32_t al2 = *(const uint32_t*)(pal + 16);
            uint32_t al3 = *(const uint32_t*)(pal + 8 * S1ROW + 16);
#pragma unroll
            for (int nt = 0; nt < 8; nt++) {
                const char* pbh = sm + G1_BHI + (nt * 8 + g) * S1ROW + (k0 + c * 2) * 2;
                const char* pbl = sm + G1_BLO + (nt * 8 + g) * S1ROW + (k0 + c * 2) * 2;
                uint32_t bh0 = *(const uint32_t*)(pbh);
                uint32_t bh1 = *(const uint32_t*)(pbh + 16);
                uint32_t bl0 = *(const uint32_t*)(pbl);
                uint32_t bl1 = *(const uint32_t*)(pbl + 16);
                mma_bf16(d[nt], ah0, ah1, ah2, ah3, bh0, bh1);
                mma_bf16(d[nt], ah0, ah1, ah2, ah3, bl0, bl1);
                mma_bf16(d[nt], al0, al1, al2, al3, bh0, bh1);
            }
        }
    }

    int r1 = row0 + wid * 16 + g, r2 = r1 + 8;
#pragma unroll
    for (int nt = 0; nt < 8; nt++) {
        if (r1 < NN) *(float2*)&g_xw1[(size_t)r1 * C1 + nt * 8 + c * 2] = make_float2(d[nt][0], d[nt][1]);
        if (r2 < NN) *(float2*)&g_xw1[(size_t)r2 * C1 + nt * 8 + c * 2] = make_float2(d[nt][2], d[nt][3]);
    }
#pragma unroll
    for (int h = 0; h < 8; h++) {
        int wcol = h * 8 + c * 2;
        float s1 = d[h][0] * ws[wcol] + d[h][1] * ws[wcol + 1];
        float t1 = d[h][0] * ws[64 + wcol] + d[h][1] * ws[64 + wcol + 1];
        float s2 = d[h][2] * ws[wcol] + d[h][3] * ws[wcol + 1];
        float t2 = d[h][2] * ws[64 + wcol] + d[h][3] * ws[64 + wcol + 1];
#pragma unroll
        for (int mk = 1; mk <= 2; mk <<= 1) {
            s1 += __shfl_xor_sync(0xffffffffu, s1, mk);
            t1 += __shfl_xor_sync(0xffffffffu, t1, mk);
            s2 += __shfl_xor_sync(0xffffffffu, s2, mk);
            t2 += __shfl_xor_sync(0xffffffffu, t2, mk);
        }
        if (c == 0) {
            if (r1 < NN) { g_al1s[r1 * NH + h] = s1; g_al1d[r1 * NH + h] = t1; }
            if (r2 < NN) { g_al1s[r2 * NH + h] = s2; g_al1d[r2 * NH + h] = t2; }
        }
    }
}

// ============ GEMM2 (mma.sync bf16x3): xw2 = h1 @ W2, fused al2 =============
#define G2_WS  0
#define G2_AHI 1024
#define G2_ALO (G2_AHI + 128 * S1ROW)
#define G2_BHI (G2_ALO + 128 * S1ROW)
#define G2_BLO (G2_BHI + 128 * S1ROW)
#define G2_SMEM (G2_BLO + 128 * S1ROW)

__global__ __launch_bounds__(256) void gemm2_m(
    const float* __restrict__ W,
    const float* __restrict__ a2s, const float* __restrict__ a2d) {
    extern __shared__ char sm[];
    float* ws = (float*)(sm + G2_WS);
    int tid = threadIdx.x, wid = tid >> 5, lid = tid & 31;
    int g = lid >> 2, c = lid & 3;
    int row0 = blockIdx.x * 128;

    if (tid < 128) ws[tid] = a2s[tid];
    else ws[tid] = a2d[tid - 128];

#pragma unroll
    for (int it = 0; it < 8; it++) {
        int idx = tid + it * 256;
        int r = idx >> 4, k = (idx & 15) << 2;
        int gr = row0 + r;
        float4 v = (gr < NN) ? *(const float4*)&g_h1[(size_t)gr * C1 + k]
                             : make_float4(0.f, 0.f, 0.f, 0.f);
        uint32_t h0 = pkbf(v.x, v.y), h1 = pkbf(v.z, v.w);
        uint32_t l0 = pkbf(v.x - __bfloat162float(__float2bfloat16(v.x)),
                           v.y - __bfloat162float(__float2bfloat16(v.y)));
        uint32_t l1 = pkbf(v.z - __bfloat162float(__float2bfloat16(v.z)),
                           v.w - __bfloat162float(__float2bfloat16(v.w)));
        *(uint2*)(sm + G2_AHI + r * S1ROW + k * 2) = make_uint2(h0, h1);
        *(uint2*)(sm + G2_ALO + r * S1ROW + k * 2) = make_uint2(l0, l1);
    }
#pragma unroll
    for (int it = 0; it < 8; it++) {
        int idx = tid + it * 256;
        int n = idx & 127, k = (idx >> 7) << 2;
        float v0 = W[(k) * 128 + n];
        float v1 = W[(k + 1) * 128 + n];
        float v2 = W[(k + 2) * 128 + n];
        float v3 = W[(k + 3) * 128 + n];
        uint32_t h0 = pkbf(v0, v1), h1 = pkbf(v2, v3);
        uint32_t l0 = pkbf(v0 - __bfloat162float(__float2bfloat16(v0)),
                           v1 - __bfloat162float(__float2bfloat16(v1)));
        uint32_t l1 = pkbf(v2 - __bfloat162float(__float2bfloat16(v2)),
                           v3 - __bfloat162float(__float2bfloat16(v3)));
        *(uint2*)(sm + G2_BHI + n * S1ROW + k * 2) = make_uint2(h0, h1);
        *(uint2*)(sm + G2_BLO + n * S1ROW + k * 2) = make_uint2(l0, l1);
    }
    __syncthreads();

    float d[16][4];
#pragma unroll
    for (int nt = 0; nt < 16; nt++)
#pragma unroll
        for (int q = 0; q < 4; q++) d[nt][q] = 0.f;

#pragma unroll
    for (int ks = 0; ks < 4; ks++) {
        int k0 = ks * 16;
        const char* pah = sm + G2_AHI + (wid * 16 + g) * S1ROW + (k0 + c * 2) * 2;
        const char* pal = sm + G2_ALO + (wid * 16 + g) * S1ROW + (k0 + c * 2) * 2;
        uint32_t ah0 = *(const uint32_t*)(pah);
        uint32_t ah1 = *(const uint32_t*)(pah + 8 * S1ROW);
        uint32_t ah2 = *(const uint32_t*)(pah + 16);
        uint32_t ah3 = *(const uint32_t*)(pah + 8 * S1ROW + 16);
        uint32_t al0 = *(const uint32_t*)(pal);
        uint32_t al1 = *(const uint32_t*)(pal + 8 * S1ROW);
        uint32_t al2 = *(const uint32_t*)(pal + 16);
        uint32_t al3 = *(const uint32_t*)(pal + 8 * S1ROW + 16);
#pragma unroll
        for (int nt = 0; nt < 16; nt++) {
            const char* pbh = sm + G2_BHI + (nt * 8 + g) * S1ROW + (k0 + c * 2) * 2;
            const char* pbl = sm + G2_BLO + (nt * 8 + g) * S1ROW + (k0 + c * 2) * 2;
            uint32_t bh0 = *(const uint32_t*)(pbh);
            uint32_t bh1 = *(const uint32_t*)(pbh + 16);
            uint32_t bl0 = *(const uint32_t*)(pbl);
            uint32_t bl1 = *(const uint32_t*)(pbl + 16);
            mma_bf16(d[nt], ah0, ah1, ah2, ah3, bh0, bh1);
            mma_bf16(d[nt], ah0, ah1, ah2, ah3, bl0, bl1);
            mma_bf16(d[nt], al0, al1, al2, al3, bh0, bh1);
        }
    }

    int r1 = row0 + wid * 16 + g, r2 = r1 + 8;
#pragma unroll
    for (int nt = 0; nt < 16; nt++) {
        if (r1 < NN) *(float2*)&g_xw2[(size_t)r1 * C2 + nt * 8 + c * 2] = make_float2(d[nt][0], d[nt][1]);
        if (r2 < NN) *(float2*)&g_xw2[(size_t)r2 * C2 + nt * 8 + c * 2] = make_float2(d[nt][2], d[nt][3]);
    }
#pragma unroll
    for (int h = 0; h < 8; h++) {
        float s1 = 0.f, t1 = 0.f, s2 = 0.f, t2 = 0.f;
#pragma unroll
        for (int sub = 0; sub < 2; sub++) {
            int nt = h * 2 + sub;
            int wcol = nt * 8 + c * 2;
            s1 += d[nt][0] * ws[wcol] + d[nt][1] * ws[wcol + 1];
            t1 += d[nt][0] * ws[128 + wcol] + d[nt][1] * ws[128 + wcol + 1];
            s2 += d[nt][2] * ws[wcol] + d[nt][3] * ws[wcol + 1];
            t2 += d[nt][2] * ws[128 + wcol] + d[nt][3] * ws[128 + wcol + 1];
        }
#pragma unroll
        for (int mk = 1; mk <= 2; mk <<= 1) {
            s1 += __shfl_xor_sync(0xffffffffu, s1, mk);
            t1 += __shfl_xor_sync(0xffffffffu, t1, mk);
            s2 += __shfl_xor_sync(0xffffffffu, s2, mk);
            t2 += __shfl_xor_sync(0xffffffffu, t2, mk);
        }
        if (c == 0) {
            if (r1 < NN) { g_al2s[r1 * NH + h] = s1; g_al2d[r1 * NH + h] = t1; }
            if (r2 < NN) { g_al2s[r2 * NH + h] = s2; g_al2d[r2 * NH + h] = t2; }
        }
    }
}

// ---------- GAT layer 1: smem transpose-reduce, alpha from regs ------------
__global__ __launch_bounds__(256) void gat1_k(float* __restrict__ alpha_out,
                                              const float* __restrict__ b1,
                                              int alpha_rows) {
    __shared__ float s_al[8][8][MAXD + 2];   // [warp][head][slot]
    __shared__ int   s_sr[8][MAXD];
    __shared__ float s_red[8][8][33];        // [warp][head][lane]
    int w = threadIdx.x >> 5, lane = threadIdx.x & 31;
    int n = blockIdx.x * 8 + w;
    int deg = g_cur[n]; if (deg > MAXD) deg = MAXD;
    int base = n * MAXD;

    float4 d0 = *(const float4*)&g_al1d[n * NH];
    float4 d1 = *(const float4*)&g_al1d[n * NH + 4];
    float ald[8] = {d0.x, d0.y, d0.z, d0.w, d1.x, d1.y, d1.z, d1.w};

    float e[2][8];
    int   srt[2];
    float s[8];
#pragma unroll
    for (int h = 0; h < 8; h++) s[h] = 0.f;
    int ns = 0;
    for (int i = lane; i < deg; i += 32) {
        int sr = __ldg(&g_srcs[base + i]);
        srt[ns] = sr;
        float4 a0 = __ldg((const float4*)&g_al1s[sr * NH]);
        float4 a1 = __ldg((const float4*)&g_al1s[sr * NH + 4]);
        float ev[8] = {a0.x, a0.y, a0.z, a0.w, a1.x, a1.y, a1.z, a1.w};
#pragma unroll
        for (int h = 0; h < 8; h++) {
            float t = ev[h] + ald[h];
            t = t > 0.f ? t : NEG_SLOPE * t;
            t = __expf(t);
            e[ns][h] = t;
            s[h] += t;
        }
        ns++;
    }
    // transpose-reduce: lane partials -> smem; group (h = lane>>2) sums
#pragma unroll
    for (int h = 0; h < 8; h++) s_red[w][h][lane] = s[h];
    __syncwarp();
    int hg = lane >> 2, j = lane & 3;
    float part = 0.f;
#pragma unroll
    for (int k = 0; k < 8; k++) part += s_red[w][hg][j * 8 + k];
    part += __shfl_xor_sync(0xffffffffu, part, 1);
    part += __shfl_xor_sync(0xffffffffu, part, 2);
    float invh = 1.f / (part + 1e-16f);
    float inv[8];
#pragma unroll
    for (int h = 0; h < 8; h++)
        inv[h] = __shfl_sync(0xffffffffu, invh, h * 4);

    // normalize from registers; park alpha + src in smem; write alpha out
    {
        int t = 0;
        for (int i = lane; i < deg; i += 32, t++) {
            float al[8];
#pragma unroll
            for (int h = 0; h < 8; h++) al[h] = e[t][h] * inv[h];
            s_sr[w][i] = srt[t];
#pragma unroll
            for (int h = 0; h < 8; h++) s_al[w][h][i] = al[h];
            int eid = __ldg(&g_eid[base + i]);
            if (eid < alpha_rows) {
                *(float4*)&alpha_out[(size_t)eid * NH]     = make_float4(al[0], al[1], al[2], al[3]);
                *(float4*)&alpha_out[(size_t)eid * NH + 4] = make_float4(al[4], al[5], al[6], al[7]);
            }
        }
    }
    __syncwarp();

    // coalesced feature accumulation, unrolled x4
    int hme = lane >> 2;
    const float2* xb = (const float2*)g_xw1 + lane;   // + sr*32 per row
    float acc0 = 0.f, acc1 = 0.f;
    int i = 0;
    for (; i + 4 <= deg; i += 4) {
        int sr0 = s_sr[w][i],     sr1 = s_sr[w][i + 1];
        int sr2 = s_sr[w][i + 2], sr3 = s_sr[w][i + 3];
        float a0 = s_al[w][hme][i],     a1 = s_al[w][hme][i + 1];
        float a2 = s_al[w][hme][i + 2], a3 = s_al[w][hme][i + 3];
        float2 v0 = __ldg(xb + sr0 * 32);
        float2 v1 = __ldg(xb + sr1 * 32);
        float2 v2 = __ldg(xb + sr2 * 32);
        float2 v3 = __ldg(xb + sr3 * 32);
        acc0 += a0 * v0.x + a1 * v1.x + a2 * v2.x + a3 * v3.x;
        acc1 += a0 * v0.y + a1 * v1.y + a2 * v2.y + a3 * v3.y;
    }
    for (; i < deg; i++) {
        int sr = s_sr[w][i];
        float a = s_al[w][hme][i];
        float2 v = __ldg(xb + sr * 32);
        acc0 += a * v.x;
        acc1 += a * v.y;
    }
    int f = lane * 2;
    float2 bb = __ldg((const float2*)&b1[f]);
    float v0 = acc0 + bb.x, v1 = acc1 + bb.y;
    v0 = v0 > 0.f ? v0 : (__expf(v0) - 1.f);   // ELU
    v1 = v1 > 0.f ? v1 : (__expf(v1) - 1.f);
    *(float2*)&g_h1[(size_t)n * C1 + f] = make_float2(v0, v1);
}

// ---------- GAT layer 2: raw-e smem, transpose-reduce (own head only) ------
__global__ __launch_bounds__(256) void gat2_k(float* __restrict__ logp,
                                              const float* __restrict__ b2) {
    __shared__ float s_al[8][8][MAXD + 2];
    __shared__ int   s_sr[8][MAXD];
    __shared__ float s_red[8][8][33];
    int w = threadIdx.x >> 5, lane = threadIdx.x & 31;
    int n = blockIdx.x * 8 + w;
    int deg = g_cur[n]; if (deg > MAXD) deg = MAXD;
    int base = n * MAXD;

    float4 d0 = *(const float4*)&g_al2d[n * NH];
    float4 d1 = *(const float4*)&g_al2d[n * NH + 4];
    float ald[8] = {d0.x, d0.y, d0.z, d0.w, d1.x, d1.y, d1.z, d1.w};

    float s[8];
#pragma unroll
    for (int h = 0; h < 8; h++) s[h] = 0.f;
    for (int i = lane; i < deg; i += 32) {
        int sr = __ldg(&g_srcs[base + i]);
        s_sr[w][i] = sr;
        float4 a0 = __ldg((const float4*)&g_al2s[sr * NH]);
        float4 a1 = __ldg((const float4*)&g_al2s[sr * NH + 4]);
        float ev[8] = {a0.x, a0.y, a0.z, a0.w, a1.x, a1.y, a1.z, a1.w};
#pragma unroll
        for (int h = 0; h < 8; h++) {
            float t = ev[h] + ald[h];
            t = t > 0.f ? t : NEG_SLOPE * t;
            t = __expf(t);
            s_al[w][h][i] = t;
            s[h] += t;
        }
    }
    // transpose-reduce: only own head's inv needed
#pragma unroll
    for (int h = 0; h < 8; h++) s_red[w][h][lane] = s[h];
    __syncwarp();
    int hme = lane >> 2, j = lane & 3;
    float part = 0.f;
#pragma unroll
    for (int k = 0; k < 8; k++) part += s_red[w][hme][j * 8 + k];
    part += __shfl_xor_sync(0xffffffffu, part, 1);
    part += __shfl_xor_sync(0xffffffffu, part, 2);
    float iv = 1.f / (part + 1e-16f);

    const float4* xb = (const float4*)g_xw2 + lane;   // + sr*32 per row
    float acc[4] = {0.f, 0.f, 0.f, 0.f};
    int i = 0;
    for (; i + 4 <= deg; i += 4) {
        int sr0 = s_sr[w][i],     sr1 = s_sr[w][i + 1];
        int sr2 = s_sr[w][i + 2], sr3 = s_sr[w][i + 3];
        float a0 = s_al[w][hme][i],     a1 = s_al[w][hme][i + 1];
        float a2 = s_al[w][hme][i + 2], a3 = s_al[w][hme][i + 3];
        float4 v0 = __ldg(xb + sr0 * 32);
        float4 v1 = __ldg(xb + sr1 * 32);
        float4 v2 = __ldg(xb + sr2 * 32);
        float4 v3 = __ldg(xb + sr3 * 32);
        acc[0] += a0 * v0.x + a1 * v1.x + a2 * v2.x + a3 * v3.x;
        acc[1] += a0 * v0.y + a1 * v1.y + a2 * v2.y + a3 * v3.y;
        acc[2] += a0 * v0.z + a1 * v1.z + a2 * v2.z + a3 * v3.z;
        acc[3] += a0 * v0.w + a1 * v1.w + a2 * v2.w + a3 * v3.w;
    }
    for (; i < deg; i++) {
        int sr = s_sr[w][i];
        float a = s_al[w][hme][i];
        float4 v = __ldg(xb + sr * 32);
        acc[0] += a * v.x; acc[1] += a * v.y;
        acc[2] += a * v.z; acc[3] += a * v.w;
    }
    int f = lane * 4;
    float4 bb = __ldg((const float4*)&b2[f]);
    float v[4] = {acc[0] * iv + bb.x, acc[1] * iv + bb.y,
                  acc[2] * iv + bb.z, acc[3] * iv + bb.w};

    float mx = fmaxf(fmaxf(v[0], v[1]), fmaxf(v[2], v[3]));
#pragma unroll
    for (int off = 16; off >= 1; off >>= 1)
        mx = fmaxf(mx, __shfl_xor_sync(0xffffffffu, mx, off));
    float se = 0.f;
#pragma unroll
    for (int q = 0; q < 4; q++) se += __expf(v[q] - mx);
#pragma unroll
    for (int off = 16; off >= 1; off >>= 1)
        se += __shfl_xor_sync(0xffffffffu, se, off);
    float lse = mx + __logf(se);
    *(float4*)&logp[(size_t)n * C2 + f] =
        make_float4(v[0] - lse, v[1] - lse, v[2] - lse, v[3] - lse);
}

// ---------------- launch ---------------------------------------------------
extern "C" void kernel_launch(void* const* d_in, const int* in_sizes, int n_in,
                              void* d_out, int out_size) {
    const float* x   = (const float*)d_in[0];
    const int*   ei  = (const int*)d_in[1];
    const float* W1  = (const float*)d_in[2];
    const float* a1s = (const float*)d_in[3];
    const float* a1d = (const float*)d_in[4];
    const float* b1  = (const float*)d_in[5];
    const float* W2  = (const float*)d_in[6];
    const float* a2s = (const float*)d_in[7];
    const float* a2d = (const float*)d_in[8];
    const float* b2  = (const float*)d_in[9];

    float* out   = (float*)d_out;
    float* logp  = out;                // [NN, 128]
    float* alpha = out + NN * C2;      // [E+loops, 8]
    int alpha_rows = (out_size - NN * C2) / NH;
    if (alpha_rows < 0) alpha_rows = 0;

    static cudaStream_t s_side = nullptr;
    static cudaEvent_t  ev_fork = nullptr, ev_join = nullptr;
    if (s_side == nullptr) {
        cudaStreamCreateWithFlags(&s_side, cudaStreamNonBlocking);
        cudaEventCreateWithFlags(&ev_fork, cudaEventDisableTiming);
        cudaEventCreateWithFlags(&ev_join, cudaEventDisableTiming);
        cudaFuncSetAttribute(gemm1_m, cudaFuncAttributeMaxDynamicSharedMemorySize, G1_SMEM);
        cudaFuncSetAttribute(gemm2_m, cudaFuncAttributeMaxDynamicSharedMemorySize, G2_SMEM);
    }

    // fork: padded-CSR build on side stream, concurrent with gemm1
    cudaEventRecord(ev_fork, 0);
    cudaStreamWaitEvent(s_side, ev_fork, 0);

    zero_cur_k<<<(NN / 4 + 256) / 256, 256, 0, s_side>>>();
    {
        const int nthr = EIN / 8 + (NN + 7) / 8;
        scatter_k<<<(nthr + 255) / 256, 256, 0, s_side>>>(ei);
    }
    cudaEventRecord(ev_join, s_side);

    gemm1_m<<<(NN + 127) / 128, 256, G1_SMEM>>>(x, W1, a1s, a1d);

    cudaStreamWaitEvent(0, ev_join, 0);

    gat1_k<<<NN / 8, 256>>>(alpha, b1, alpha_rows);
    gemm2_m<<<(NN + 127) / 128, 256, G2_SMEM>>>(W2, a2s, a2d);
    gat2_k<<<NN / 8, 256>>>(logp, b2);
}